// round 1
// baseline (speedup 1.0000x reference)
#include <cuda_runtime.h>

#define BB 256
#define TT 512
#define DIN 64
#define HH 128
#define G3 384

typedef unsigned long long u64;

// ---------- f32x2 packed helpers (Blackwell) ----------
__device__ __forceinline__ u64 f2fma(u64 a, u64 b, u64 c) {
    u64 d; asm("fma.rn.f32x2 %0, %1, %2, %3;" : "=l"(d) : "l"(a), "l"(b), "l"(c)); return d;
}
__device__ __forceinline__ u64 f2add(u64 a, u64 b) {
    u64 d; asm("add.rn.f32x2 %0, %1, %2;" : "=l"(d) : "l"(a), "l"(b)); return d;
}
__device__ __forceinline__ u64 pack2(float w) {
    u64 d; asm("mov.b64 %0, {%1, %1};" : "=l"(d) : "f"(w)); return d;
}
__device__ __forceinline__ u64 pack2f(float x, float y) {
    u64 d; asm("mov.b64 %0, {%1, %2};" : "=l"(d) : "f"(x), "f"(y)); return d;
}
__device__ __forceinline__ float2 unpack2(u64 v) {
    float2 r; asm("mov.b64 {%0, %1}, %2;" : "=f"(r.x), "=f"(r.y) : "l"(v)); return r;
}

// ---------- device scratch (no allocations allowed) ----------
__device__ float d_Wn_t[HH * HH];      // [k][j]
__device__ float d_Whh_q[HH * G3];     // quad-interleaved: [(k>>2)][o][k&3]
__device__ float d_Wih_q[DIN * G3];    // quad-interleaved
__device__ float d_Wout_q[HH * DIN];   // quad-interleaved
__device__ float d_dts[TT];
__device__ unsigned char d_mask[TT];

// ---------- prologue: transposes, dts, mask canonicalization ----------
__global__ void prep_kernel(const float* __restrict__ W_ih,
                            const float* __restrict__ W_hh,
                            const float* __restrict__ W_node,
                            const float* __restrict__ W_out,
                            const float* __restrict__ tp,
                            const unsigned char* __restrict__ mask_raw)
{
    int i = blockIdx.x * blockDim.x + threadIdx.x;

    if (i < HH * G3) { int o = i / HH, k = i % HH;
        d_Whh_q[(k >> 2) * (G3 * 4) + o * 4 + (k & 3)] = W_hh[i]; }
    if (i < DIN * G3) { int o = i / DIN, k = i % DIN;
        d_Wih_q[(k >> 2) * (G3 * 4) + o * 4 + (k & 3)] = W_ih[i]; }
    if (i < HH * HH) { int j = i / HH, k = i % HH;
        d_Wn_t[k * HH + j] = W_node[i]; }
    if (i < HH * DIN) { int o = i / HH, k = i % HH;
        d_Wout_q[(k >> 2) * (DIN * 4) + o * 4 + (k & 3)] = W_out[i]; }
    if (i < TT) d_dts[i] = (i == 0) ? 0.01f : (tp[i] - tp[i - 1]);

    // mask dtype sniffing: a genuine uint8 0/1 mask must have a nonzero byte
    // at some index not divisible by 4; float32 shows 0x3f at 4i+3.
    if (blockIdx.x == 0) {
        __shared__ int s_off4, s_f32;
        if (threadIdx.x == 0) { s_off4 = 0; s_f32 = 0; }
        __syncthreads();
        for (int k = threadIdx.x; k < TT; k += blockDim.x)
            if (mask_raw[k] != 0 && (k & 3) != 0) atomicOr(&s_off4, 1);
        for (int k = threadIdx.x; k < TT / 4; k += blockDim.x)
            if (mask_raw[4 * k + 3] == 0x3f) atomicOr(&s_f32, 1);
        __syncthreads();
        bool word = (s_off4 == 0) || (s_f32 != 0);   // int32 or float32 payload
        const int* mi = (const int*)mask_raw;
        for (int k = threadIdx.x; k < TT; k += blockDim.x)
            d_mask[k] = word ? (unsigned char)(mi[k] != 0)
                             : (unsigned char)(mask_raw[k] != 0);
    }
}

// ---------- main persistent kernel: 128 blocks x 512 threads, 2 samples/block ----------
#define SMEM_WHH   0
#define SMEM_H2    196608
#define SMEM_HTMP  197632
#define SMEM_HODE  198656
#define SMEM_INP   199680
#define SMEM_LOUT  200192
#define SMEM_SCR   200704
#define SMEM_BYTES 204800

__global__ __launch_bounds__(512, 1)
void gruode_kernel(const float* __restrict__ x,
                   const float* __restrict__ b_ih,
                   const float* __restrict__ b_hh,
                   const float* __restrict__ b_node,
                   const float* __restrict__ b_out,
                   float* __restrict__ out)
{
    extern __shared__ char smem[];
    float* Whh_s    = (float*)(smem + SMEM_WHH);    // 192 KB, quad layout
    u64*   h2       = (u64*)(smem + SMEM_H2);       // [128] packed pair-state
    u64*   htmp2    = (u64*)(smem + SMEM_HTMP);
    u64*   hode2    = (u64*)(smem + SMEM_HODE);
    u64*   inp2     = (u64*)(smem + SMEM_INP);      // [64]
    u64*   lastout2 = (u64*)(smem + SMEM_LOUT);     // [64]
    u64*   scratch  = (u64*)(smem + SMEM_SCR);      // [512]

    const int t  = threadIdx.x;
    const int s0 = 2 * blockIdx.x;
    const int s1 = s0 + 1;
    const int c  = t >> 7;      // RK4 k-chunk (0..3, 32 k each)
    const int j  = t & 127;     // RK4 output index

    // Stage W_hh into smem (prologue already wrote the quad layout)
    {
        const float4* src = (const float4*)d_Whh_q;
        float4* dst = (float4*)Whh_s;
        for (int i = t; i < (HH * G3) / 4; i += 512) dst[i] = src[i];
    }

    // W_node slice lives in registers, pre-duplicated for f32x2
    u64 wreg[32];
    #pragma unroll
    for (int kk = 0; kk < 32; kk++)
        wreg[kk] = pack2(d_Wn_t[(c * 32 + kk) * HH + j]);

    float bnj = 0.f, bihO = 0.f, bhhO = 0.f, boutO = 0.f;
    if (t < HH) bnj = b_node[j];
    if (t < G3) { bihO = b_ih[t]; bhhO = b_hh[t]; }
    if (t < DIN) boutO = b_out[t];

    if (t < HH) h2[t] = 0ull;                    // h0 = 0
    if (t < DIN) lastout2[t] = pack2(boutO);     // out(h0) = b_out
    __syncthreads();

    // node matvec: partial dot over this thread's 32-k chunk, both samples packed
    auto mv = [&](const u64* src) {
        const ulonglong2* s2 = (const ulonglong2*)(src + c * 32);
        u64 a0 = 0ull, a1 = 0ull;
        #pragma unroll
        for (int kk = 0; kk < 32; kk += 2) {
            ulonglong2 hv = s2[kk >> 1];
            a0 = f2fma(wreg[kk],     hv.x, a0);
            a1 = f2fma(wreg[kk + 1], hv.y, a1);
        }
        scratch[c * 128 + j] = f2add(a0, a1);
    };
    auto combine = [&]() -> float2 {
        u64 s = f2add(f2add(scratch[j], scratch[128 + j]),
                      f2add(scratch[256 + j], scratch[384 + j]));
        float2 v = unpack2(s);
        return make_float2(tanhf(v.x + bnj), tanhf(v.y + bnj));
    };

    for (int st = 0; st < TT; st++) {
        const float dt  = d_dts[st];
        const float hdt = 0.5f * dt;
        const float dt6 = dt * (1.0f / 6.0f);

        // input vector: x if sampled, else previous step's own output
        if (t < DIN) {
            if (d_mask[st])
                inp2[t] = pack2f(x[(s0 * TT + st) * DIN + t],
                                 x[(s1 * TT + st) * DIN + t]);
            else
                inp2[t] = lastout2[t];
        }

        // ---- RK4: h_ode = rk4(h, dt) ----
        float2 ksx = make_float2(0.f, 0.f), hbase = make_float2(0.f, 0.f);
        mv(h2); __syncthreads();
        if (t < HH) {
            float2 k1 = combine();
            hbase = unpack2(h2[j]);
            ksx = k1;
            htmp2[j] = pack2f(hbase.x + hdt * k1.x, hbase.y + hdt * k1.y);
        }
        __syncthreads();
        mv(htmp2); __syncthreads();
        if (t < HH) {
            float2 k2 = combine();
            ksx.x += 2.f * k2.x; ksx.y += 2.f * k2.y;
            htmp2[j] = pack2f(hbase.x + hdt * k2.x, hbase.y + hdt * k2.y);
        }
        __syncthreads();
        mv(htmp2); __syncthreads();
        if (t < HH) {
            float2 k3 = combine();
            ksx.x += 2.f * k3.x; ksx.y += 2.f * k3.y;
            htmp2[j] = pack2f(hbase.x + dt * k3.x, hbase.y + dt * k3.y);
        }
        __syncthreads();
        mv(htmp2); __syncthreads();
        if (t < HH) {
            float2 k4 = combine();
            hode2[j] = pack2f(hbase.x + dt6 * (ksx.x + k4.x),
                              hbase.y + dt6 * (ksx.y + k4.y));
        }
        __syncthreads();

        // ---- GRU gates: one gate-row per thread (o < 384) ----
        if (t < G3) {
            const int o = t;
            // gi = inp @ W_ih^T + b_ih   (k = 0..63, L1-resident weights)
            u64 ai0 = pack2(bihO), ai1 = 0ull;
            const float4* wq = (const float4*)d_Wih_q;
            const ulonglong2* ip = (const ulonglong2*)inp2;
            #pragma unroll
            for (int q = 0; q < DIN / 4; q++) {
                float4 w = __ldg(&wq[q * G3 + o]);
                ulonglong2 hA = ip[2 * q], hB = ip[2 * q + 1];
                ai0 = f2fma(pack2(w.x), hA.x, ai0);
                ai1 = f2fma(pack2(w.y), hA.y, ai1);
                ai0 = f2fma(pack2(w.z), hB.x, ai0);
                ai1 = f2fma(pack2(w.w), hB.y, ai1);
            }
            u64 ai = f2add(ai0, ai1);
            // gh = h_ode @ W_hh^T + b_hh (k = 0..127, smem weights)
            u64 ah0 = pack2(bhhO), ah1 = 0ull;
            const float4* wh = (const float4*)Whh_s;
            const ulonglong2* hp = (const ulonglong2*)hode2;
            #pragma unroll 8
            for (int q = 0; q < HH / 4; q++) {
                float4 w = wh[q * G3 + o];
                ulonglong2 hA = hp[2 * q], hB = hp[2 * q + 1];
                ah0 = f2fma(pack2(w.x), hA.x, ah0);
                ah1 = f2fma(pack2(w.y), hA.y, ah1);
                ah0 = f2fma(pack2(w.z), hB.x, ah0);
                ah1 = f2fma(pack2(w.w), hB.y, ah1);
            }
            u64 ah = f2add(ah0, ah1);
            if (o < 256) {      // r (o<128) and z (o<256): sigmoid(gi+gh)
                float2 g = unpack2(f2add(ai, ah));
                scratch[o] = pack2f(1.f / (1.f + __expf(-g.x)),
                                    1.f / (1.f + __expf(-g.y)));
            } else {            // n-gate pieces: keep i_n and h_n separate
                scratch[o] = ai;
                scratch[o + 128] = ah;
            }
        }
        __syncthreads();

        // ---- GRU combine: h = (1-z)*n + z*h_ode ----
        if (t < HH) {
            float2 r  = unpack2(scratch[j]);
            float2 z  = unpack2(scratch[128 + j]);
            float2 in_= unpack2(scratch[256 + j]);
            float2 hn = unpack2(scratch[384 + j]);
            float2 ho = unpack2(hode2[j]);
            float nx = tanhf(in_.x + r.x * hn.x);
            float ny = tanhf(in_.y + r.y * hn.y);
            h2[j] = pack2f((1.f - z.x) * nx + z.x * ho.x,
                           (1.f - z.y) * ny + z.y * ho.y);
        }
        __syncthreads();

        // ---- output projection: out = h @ W_out^T + b_out (8-way k-split) ----
        {
            const int o = t & 63, cc = t >> 6;
            const float4* wo = (const float4*)d_Wout_q;
            const ulonglong2* hp = (const ulonglong2*)h2;
            u64 a0 = 0ull, a1 = 0ull;
            #pragma unroll
            for (int qq = 0; qq < 4; qq++) {
                int q = cc * 4 + qq;
                float4 w = __ldg(&wo[q * DIN + o]);
                ulonglong2 hA = hp[2 * q], hB = hp[2 * q + 1];
                a0 = f2fma(pack2(w.x), hA.x, a0);
                a1 = f2fma(pack2(w.y), hA.y, a1);
                a0 = f2fma(pack2(w.z), hB.x, a0);
                a1 = f2fma(pack2(w.w), hB.y, a1);
            }
            scratch[cc * 64 + o] = f2add(a0, a1);
        }
        __syncthreads();
        if (t < DIN) {
            u64 s = scratch[t];
            #pragma unroll
            for (int cc = 1; cc < 8; cc++) s = f2add(s, scratch[cc * 64 + t]);
            float2 v = unpack2(s);
            v.x += boutO; v.y += boutO;
            out[(s0 * TT + st) * DIN + t] = v.x;
            out[(s1 * TT + st) * DIN + t] = v.y;
            lastout2[t] = pack2f(v.x, v.y);
        }
        __syncthreads();
    }
}

extern "C" void kernel_launch(void* const* d_in, const int* in_sizes, int n_in,
                              void* d_out, int out_size)
{
    (void)in_sizes; (void)n_in; (void)out_size;
    const float* x       = (const float*)d_in[0];
    const float* tp      = (const float*)d_in[1];
    const unsigned char* mask = (const unsigned char*)d_in[2];
    const float* W_ih    = (const float*)d_in[3];
    const float* W_hh    = (const float*)d_in[4];
    const float* b_ih    = (const float*)d_in[5];
    const float* b_hh    = (const float*)d_in[6];
    const float* W_node  = (const float*)d_in[7];
    const float* b_node  = (const float*)d_in[8];
    const float* W_out   = (const float*)d_in[9];
    const float* b_out   = (const float*)d_in[10];
    float* out = (float*)d_out;

    prep_kernel<<<192, 256>>>(W_ih, W_hh, W_node, W_out, tp, mask);

    cudaFuncSetAttribute(gruode_kernel,
                         cudaFuncAttributeMaxDynamicSharedMemorySize, SMEM_BYTES);
    gruode_kernel<<<BB / 2, 512, SMEM_BYTES>>>(x, b_ih, b_hh, b_node, b_out, out);
}

// round 2
// speedup vs baseline: 1.3594x; 1.3594x over previous
#include <cuda_runtime.h>

#define TT 512
#define DIN 64
#define HH 128
#define G3 384

typedef unsigned long long u64;

// ---------- packed f32x2 helpers (halves = adjacent k) ----------
__device__ __forceinline__ u64 f2fma(u64 a, u64 b, u64 c) {
    u64 d; asm("fma.rn.f32x2 %0, %1, %2, %3;" : "=l"(d) : "l"(a), "l"(b), "l"(c)); return d;
}
__device__ __forceinline__ u64 f2add(u64 a, u64 b) {
    u64 d; asm("add.rn.f32x2 %0, %1, %2;" : "=l"(d) : "l"(a), "l"(b)); return d;
}
__device__ __forceinline__ float f2red(u64 v) {   // sum of halves
    float lo, hi; asm("mov.b64 {%0, %1}, %2;" : "=f"(lo), "=f"(hi) : "l"(v)); return lo + hi;
}
__device__ __forceinline__ float tanh_mufu(float x) {
    float y; asm("tanh.approx.f32 %0, %1;" : "=f"(y) : "f"(x)); return y;
}
__device__ __forceinline__ float sigm(float x) {
    return __fdividef(1.0f, 1.0f + __expf(-x));
}

// ---------- device scratch ----------
__device__ float d_Whh_q[HH * G3];     // float4 quads: [(k>>2)][o][k&3]
__device__ float d_dts[TT];
__device__ unsigned char d_mask[TT];

// ---------- prologue ----------
__global__ void prep_kernel(const float* __restrict__ W_hh,
                            const float* __restrict__ tp,
                            const unsigned char* __restrict__ mask_raw)
{
    int i = blockIdx.x * blockDim.x + threadIdx.x;
    if (i < HH * G3) { int o = i / HH, k = i % HH;
        d_Whh_q[(k >> 2) * (G3 * 4) + o * 4 + (k & 3)] = W_hh[i]; }
    if (i < TT) d_dts[i] = (i == 0) ? 0.01f : (tp[i] - tp[i - 1]);

    // mask dtype sniffing (uint8 vs int32/float32 marshalling)
    if (blockIdx.x == 0) {
        __shared__ int s_off4, s_f32;
        if (threadIdx.x == 0) { s_off4 = 0; s_f32 = 0; }
        __syncthreads();
        for (int k = threadIdx.x; k < TT; k += blockDim.x)
            if (mask_raw[k] != 0 && (k & 3) != 0) atomicOr(&s_off4, 1);
        for (int k = threadIdx.x; k < TT / 4; k += blockDim.x)
            if (mask_raw[4 * k + 3] == 0x3f) atomicOr(&s_f32, 1);
        __syncthreads();
        bool word = (s_off4 == 0) || (s_f32 != 0);
        const int* mi = (const int*)mask_raw;
        for (int k = threadIdx.x; k < TT; k += blockDim.x)
            d_mask[k] = word ? (unsigned char)(mi[k] != 0)
                             : (unsigned char)(mask_raw[k] != 0);
    }
}

// ---------- smem layout (bytes) ----------
#define OFF_WHH   0        // 196608 : W_hh quads
#define OFF_SCG   196608   // 16384  : GRU partials [4 quant][2 s][4 c][128 j] f32
#define OFF_SCR   196608   // 4096   : RK4 partials [2 s][4 c][128 j] (aliases SCG)
#define OFF_OUTS  212992   // 4096   : out partials [2 s][8 cc][64 oo]
#define OFF_H     217088   // 1024   : h      [2][128]
#define OFF_HTMP  218112   // 1024   : htmp   [2][128]
#define OFF_HODE  219136   // 1024   : h_ode  [2][128]
#define OFF_INP   220160   // 512    : inp    [2][64]
#define OFF_DTS   220672   // 2048
#define OFF_MASK  222720   // 512
#define SMEM_BYTES 223232

__global__ __launch_bounds__(512, 1)
void gruode_kernel(const float* __restrict__ x,
                   const float* __restrict__ W_ih,
                   const float* __restrict__ b_ih,
                   const float* __restrict__ b_hh,
                   const float* __restrict__ W_node,
                   const float* __restrict__ b_node,
                   const float* __restrict__ W_out,
                   const float* __restrict__ b_out,
                   float* __restrict__ out)
{
    extern __shared__ char smem[];
    float* Whh_s   = (float*)(smem + OFF_WHH);
    float* scg     = (float*)(smem + OFF_SCG);
    float* scr     = (float*)(smem + OFF_SCR);
    float* outs    = (float*)(smem + OFF_OUTS);
    float* h_sm    = (float*)(smem + OFF_H);
    float* htmp_sm = (float*)(smem + OFF_HTMP);
    float* hode_sm = (float*)(smem + OFF_HODE);
    float* inp_sm  = (float*)(smem + OFF_INP);
    float* sdts    = (float*)(smem + OFF_DTS);
    unsigned char* smask = (unsigned char*)(smem + OFF_MASK);

    const int t   = threadIdx.x;
    const int c4  = t >> 7;       // k-chunk 0..3 (32 k each)
    const int j   = t & 127;      // output row
    const int cc  = t >> 6;       // out-proj k-chunk 0..7
    const int oo  = t & 63;       // out-proj output
    const int bid = blockIdx.x;

    // ---- stage W_hh into smem ----
    {
        const float4* src = (const float4*)d_Whh_q;
        float4* dst = (float4*)Whh_s;
        #pragma unroll
        for (int i = 0; i < 24; i++) dst[t + 512 * i] = src[t + 512 * i];
    }
    for (int i = t; i < TT; i += 512) { sdts[i] = d_dts[i]; smask[i] = d_mask[i]; }

    // ---- register weights (k-pair packed, natural loads) ----
    u64 wn2[16];                                   // W_node[j][32c4 .. +32)
    {
        const u64* p = (const u64*)(W_node + j * HH + 32 * c4);
        #pragma unroll
        for (int i = 0; i < 16; i++) wn2[i] = p[i];
    }
    u64 wihr[8], wihz[8], wihn[8];                 // W_ih rows j, 128+j, 256+j ; k in [16c4, +16)
    {
        const u64* pr = (const u64*)(W_ih + (j)        * DIN + 16 * c4);
        const u64* pz = (const u64*)(W_ih + (HH + j)   * DIN + 16 * c4);
        const u64* pn = (const u64*)(W_ih + (2*HH + j) * DIN + 16 * c4);
        #pragma unroll
        for (int i = 0; i < 8; i++) { wihr[i] = pr[i]; wihz[i] = pz[i]; wihn[i] = pn[i]; }
    }
    u64 wout2[8];                                  // W_out[oo][16cc .. +16)
    {
        const u64* p = (const u64*)(W_out + oo * HH + 16 * cc);
        #pragma unroll
        for (int i = 0; i < 8; i++) wout2[i] = p[i];
    }

    // ---- per-thread biases / state registers ----
    float bn = 0.f, br = 0.f, bz = 0.f, bin = 0.f, bhn = 0.f;
    if (t < 256) {
        bn  = b_node[j];
        br  = b_ih[j] + b_hh[j];
        bz  = b_ih[HH + j] + b_hh[HH + j];
        bin = b_ih[2*HH + j];
        bhn = b_hh[2*HH + j];
    }
    float bout = 0.f, lastout = 0.f, xreg = 0.f;
    if (t < 128) {
        int s = t >> 6;
        bout = b_out[oo];
        lastout = bout;                             // out(h0=0) = b_out
        xreg = x[((2 * bid + s) * TT + 0) * DIN + oo];
    }
    float hbase = 0.f, ksum = 0.f;
    if (t < 256) h_sm[t] = 0.f;                     // h0 = 0
    __syncthreads();

    // node matvec partial for both samples (k-chunk c4)
    auto mv = [&](const float* src) {
        const ulonglong2* q0 = (const ulonglong2*)(src)      + 8 * c4;
        const ulonglong2* q1 = (const ulonglong2*)(src + HH) + 8 * c4;
        u64 a0 = 0, a1 = 0, b0 = 0, b1 = 0;
        #pragma unroll
        for (int p = 0; p < 8; p++) {
            ulonglong2 v0 = q0[p], v1 = q1[p];
            a0 = f2fma(wn2[2*p],   v0.x, a0);
            a1 = f2fma(wn2[2*p+1], v0.y, a1);
            b0 = f2fma(wn2[2*p],   v1.x, b0);
            b1 = f2fma(wn2[2*p+1], v1.y, b1);
        }
        scr[      c4 * HH + j] = f2red(f2add(a0, a1));
        scr[512 + c4 * HH + j] = f2red(f2add(b0, b1));
    };
    auto ksm = [&](int sC, int jC) -> float {       // combined partial + bias + tanh
        const float* b = scr + sC * 512 + jC;
        return tanh_mufu(b[0] + b[128] + b[256] + b[384] + bn);
    };

    for (int st = 0; st < TT; st++) {
        const float dt  = sdts[st];
        const float hdt = 0.5f * dt;
        const float dt6 = dt * (1.0f / 6.0f);
        const int sC = t >> 7, jC = t & 127;        // combine mapping (t<256)

        // P1: mv(h) ; t<128 writes inp + prefetches next x
        mv(h_sm);
        if (t < 128) {
            int s = t >> 6;
            inp_sm[s * DIN + oo] = smask[st] ? xreg : lastout;
            if (st + 1 < TT) xreg = x[((2 * bid + s) * TT + st + 1) * DIN + oo];
        }
        __syncthreads();
        if (t < 256) {                              // k1
            float k = ksm(sC, jC);
            ksum = k;
            htmp_sm[sC * HH + jC] = hbase + hdt * k;
        }
        __syncthreads();
        mv(htmp_sm); __syncthreads();
        if (t < 256) {                              // k2
            float k = ksm(sC, jC);
            ksum += 2.f * k;
            htmp_sm[sC * HH + jC] = hbase + hdt * k;
        }
        __syncthreads();
        mv(htmp_sm); __syncthreads();
        if (t < 256) {                              // k3
            float k = ksm(sC, jC);
            ksum += 2.f * k;
            htmp_sm[sC * HH + jC] = hbase + dt * k;
        }
        __syncthreads();
        mv(htmp_sm); __syncthreads();
        if (t < 256) {                              // k4 -> h_ode
            float k = ksm(sC, jC);
            hode_sm[sC * HH + jC] = hbase + dt6 * (ksum + k);
        }
        __syncthreads();

        // P9: GRU partials, k-chunked over all 512 threads
        {
            const ulonglong2* W2  = (const ulonglong2*)Whh_s;
            const ulonglong2* hq0 = (const ulonglong2*)(hode_sm)      + 8 * c4;
            const ulonglong2* hq1 = (const ulonglong2*)(hode_sm + HH) + 8 * c4;
            u64 r0=0, z0=0, n0=0, r1=0, z1=0, n1=0;
            #pragma unroll
            for (int qq = 0; qq < 8; qq++) {
                int b = (8 * c4 + qq) * G3;
                ulonglong2 wr = W2[b + j];
                ulonglong2 wz = W2[b + HH + j];
                ulonglong2 wn = W2[b + 2*HH + j];
                ulonglong2 h0 = hq0[qq], h1 = hq1[qq];
                r0 = f2fma(wr.x, h0.x, r0); r0 = f2fma(wr.y, h0.y, r0);
                z0 = f2fma(wz.x, h0.x, z0); z0 = f2fma(wz.y, h0.y, z0);
                n0 = f2fma(wn.x, h0.x, n0); n0 = f2fma(wn.y, h0.y, n0);
                r1 = f2fma(wr.x, h1.x, r1); r1 = f2fma(wr.y, h1.y, r1);
                z1 = f2fma(wz.x, h1.x, z1); z1 = f2fma(wz.y, h1.y, z1);
                n1 = f2fma(wn.x, h1.x, n1); n1 = f2fma(wn.y, h1.y, n1);
            }
            const u64* in0 = (const u64*)(inp_sm)       + 8 * c4;
            const u64* in1 = (const u64*)(inp_sm + DIN) + 8 * c4;
            u64 i0 = 0, i1 = 0;
            #pragma unroll
            for (int p = 0; p < 8; p++) {
                u64 a = in0[p], b = in1[p];
                r0 = f2fma(wihr[p], a, r0);
                z0 = f2fma(wihz[p], a, z0);
                i0 = f2fma(wihn[p], a, i0);
                r1 = f2fma(wihr[p], b, r1);
                z1 = f2fma(wihz[p], b, z1);
                i1 = f2fma(wihn[p], b, i1);
            }
            int o = c4 * HH + j;
            scg[0*1024 +       o] = f2red(r0);  scg[0*1024 + 512 + o] = f2red(r1);
            scg[1*1024 +       o] = f2red(z0);  scg[1*1024 + 512 + o] = f2red(z1);
            scg[2*1024 +       o] = f2red(i0);  scg[2*1024 + 512 + o] = f2red(i1);
            scg[3*1024 +       o] = f2red(n0);  scg[3*1024 + 512 + o] = f2red(n1);
        }
        __syncthreads();

        // P10: GRU combine (t<256, one thread per (sample, j))
        if (t < 256) {
            const float* b0 = scg + sC * 512 + jC;
            float sr = b0[0]      + b0[128]      + b0[256]      + b0[384];
            float sz = b0[1024]   + b0[1024+128] + b0[1024+256] + b0[1024+384];
            float si = b0[2048]   + b0[2048+128] + b0[2048+256] + b0[2048+384];
            float sn = b0[3072]   + b0[3072+128] + b0[3072+256] + b0[3072+384];
            float r = sigm(sr + br);
            float z = sigm(sz + bz);
            float n = tanhf(si + bin + r * (sn + bhn));
            float ho = hode_sm[sC * HH + jC];
            float hnew = (1.f - z) * n + z * ho;
            hbase = hnew;
            h_sm[sC * HH + jC] = hnew;
        }
        __syncthreads();

        // P11: output projection partials (all 512, 8-way k-split)
        {
            const ulonglong2* hq0 = (const ulonglong2*)(h_sm)      + 4 * cc;
            const ulonglong2* hq1 = (const ulonglong2*)(h_sm + HH) + 4 * cc;
            u64 a0 = 0, a1 = 0, b0 = 0, b1 = 0;
            #pragma unroll
            for (int p = 0; p < 4; p++) {
                ulonglong2 v = hq0[p], w = hq1[p];
                a0 = f2fma(wout2[2*p],   v.x, a0);
                a1 = f2fma(wout2[2*p+1], v.y, a1);
                b0 = f2fma(wout2[2*p],   w.x, b0);
                b1 = f2fma(wout2[2*p+1], w.y, b1);
            }
            outs[      cc * 64 + oo] = f2red(f2add(a0, a1));
            outs[512 + cc * 64 + oo] = f2red(f2add(b0, b1));
        }
        __syncthreads();

        // P12: out reduce + store + lastout (t<128; no trailing barrier —
        // next P1 touches only scr/h_sm/inp, all disjoint or same-thread)
        if (t < 128) {
            int s = t >> 6;
            const float* b = outs + s * 512 + oo;
            float v = b[0] + b[64] + b[128] + b[192] + b[256] + b[320] + b[384] + b[448] + bout;
            out[((2 * bid + s) * TT + st) * DIN + oo] = v;
            lastout = v;
        }
    }
}

extern "C" void kernel_launch(void* const* d_in, const int* in_sizes, int n_in,
                              void* d_out, int out_size)
{
    (void)in_sizes; (void)n_in; (void)out_size;
    const float* x       = (const float*)d_in[0];
    const float* tp      = (const float*)d_in[1];
    const unsigned char* mask = (const unsigned char*)d_in[2];
    const float* W_ih    = (const float*)d_in[3];
    const float* W_hh    = (const float*)d_in[4];
    const float* b_ih    = (const float*)d_in[5];
    const float* b_hh    = (const float*)d_in[6];
    const float* W_node  = (const float*)d_in[7];
    const float* b_node  = (const float*)d_in[8];
    const float* W_out   = (const float*)d_in[9];
    const float* b_out   = (const float*)d_in[10];
    float* out = (float*)d_out;

    prep_kernel<<<192, 256>>>(W_hh, tp, mask);

    cudaFuncSetAttribute(gruode_kernel,
                         cudaFuncAttributeMaxDynamicSharedMemorySize, SMEM_BYTES);
    gruode_kernel<<<128, 512, SMEM_BYTES>>>(x, W_ih, b_ih, b_hh, W_node, b_node,
                                            W_out, b_out, out);
}